// round 4
// baseline (speedup 1.0000x reference)
#include <cuda_runtime.h>
#include <math.h>

#define N_ 16384
#define D_ 2048
#define H_ 1024

// fp32(exp(-100)) = 27 * 2^-149 (subnormal), bit pattern 0x0000001B.
#define CLIP_P_BITS 27u

#define GRID_PRE  1024   // producer blocks (one Mu row each)
#define GRID_MAIN 2048   // consumer blocks (8 x rows each)
#define GRID_ALL  (GRID_PRE + GRID_MAIN)

// ---------------- scratch (device globals; no allocation allowed) ----------
__device__ float g_mu2[H_];        // ||mu_h||^2 (fallback path)
__device__ int   g_maxmu2_bits;    // atomicMax over mu2 (nonneg -> int order ok)
__device__ int   g_count;          // producer completion counter
__device__ int   g_done;           // consumer completion counter
__device__ int   g_ready;          // threshold published flag
__device__ float g_maxsd2;
__device__ float g_zconst;         // exact subnormal z for a clipped row
__device__ float g_yconst;         // y for a clipped row
__device__ float g_x2thresh;       // row clips if (partial) x2 > this

// Non-FTZ fp32 ops (immune to any -ftz / fast-math compile flags).
__device__ __forceinline__ float mul_rn(float a, float b) {
    float c; asm("mul.rn.f32 %0, %1, %2;" : "=f"(c) : "f"(a), "f"(b)); return c;
}
__device__ __forceinline__ float add_rn(float a, float b) {
    float c; asm("add.rn.f32 %0, %1, %2;" : "=f"(c) : "f"(a), "f"(b)); return c;
}

// ---------------- fused single kernel ---------------------------------------
__global__ void __launch_bounds__(256, 4) k_all(const float* __restrict__ x,
                                                const float* __restrict__ Mu,
                                                const float* __restrict__ Sd,
                                                const float* __restrict__ W,
                                                float* __restrict__ y,
                                                float* __restrict__ p) {
    __shared__ float sh[256];
    __shared__ float sh2[256];
    const int t = threadIdx.x;

    if (blockIdx.x < GRID_PRE) {
        // ================= producer: prologue ===============================
        const int row = blockIdx.x;
        const float4* r = (const float4*)(Mu + (size_t)row * D_);
        float4 a = r[t], b = r[t + 256];
        float s = a.x * a.x + a.y * a.y + a.z * a.z + a.w * a.w
                + b.x * b.x + b.y * b.y + b.z * b.z + b.w * b.w;
        sh[t] = s;
        __syncthreads();
        for (int o = 128; o > 0; o >>= 1) {
            if (t < o) sh[t] += sh[t + o];
            __syncthreads();
        }
        if (t == 0) {
            float m2 = sh[0];
            g_mu2[row] = m2;
            atomicMax(&g_maxmu2_bits, __float_as_int(m2));
        }
        __syncthreads();

        if (blockIdx.x == 0) {
            // maxsd2 + exact subnormal z over 1024 (4 per thread)
            float msd = 0.0f;
            const float C = __uint_as_float(CLIP_P_BITS);
            float zp = 0.0f;
#pragma unroll
            for (int i = 0; i < 4; i++) {
                float sd = Sd[t + 256 * i];
                msd = fmaxf(msd, sd * sd);
                // exact: products are multiples of 2^-149, |sum| << 2^-126,
                // so fp32 adds are exact and order-independent.
                zp = add_rn(zp, mul_rn(C, W[t + 256 * i]));
            }
            sh[t] = msd;
            sh2[t] = zp;
            __syncthreads();
            for (int o = 128; o > 0; o >>= 1) {
                if (t < o) {
                    sh[t] = fmaxf(sh[t], sh[t + o]);
                    sh2[t] = add_rn(sh2[t], sh2[t + o]);
                }
                __syncthreads();
            }
            if (t == 0) {
                g_maxsd2 = sh[0];
                float z = sh2[0];
                g_zconst = z;
                float tt = mul_rn(2.0f / 3.0f, z);                // subnormal-safe
                float th = (fabsf(tt) < 1e-5f) ? tt : tanhf(tt);  // tanh(x)==x tiny
                g_yconst = mul_rn(1.7159f, th);
            }
            __syncthreads();
        }

        if (t == 0) {
            __threadfence();
            int c = atomicAdd(&g_count, 1);
            if (c == GRID_PRE - 1) {   // last producer publishes the threshold
                __threadfence();
                float maxmu2 = __int_as_float(g_maxmu2_bits);
                float maxsd2 = g_maxsd2;
                // Row n clips for ALL h iff dist(n,h) > 200*sd_h^2 for all h.
                // Cauchy-Schwarz: dist >= (sqrt(x2)-sqrt(mu2_h))^2, x2>mu2_h.
                // Margins cover our fp error AND the reference's GEMM error.
                float rhs = sqrtf(maxmu2) + sqrtf(200.0f * maxsd2 * 1.001f + 4.0f);
                g_x2thresh = rhs * rhs;
                __threadfence();
                g_ready = 1;          // release
                __threadfence();
            }
        }
    } else {
        // ================= consumer: per-warp row logic =====================
        const int warp = t >> 5;
        const int lane = t & 31;
        const int n    = (blockIdx.x - GRID_PRE) * 8 + warp;
        const float4* xr = (const float4*)(x + (size_t)n * D_);

        // Stage 1: lower bound on ||x_n||^2 from first 768 elems
        // (issued BEFORE the spin so loads overlap the producers' Mu read)
        float4 v[6];
#pragma unroll
        for (int i = 0; i < 6; i++) v[i] = __ldcs(xr + lane + 32 * i);
        float s = 0.0f;
#pragma unroll
        for (int i = 0; i < 6; i++)
            s += v[i].x * v[i].x + v[i].y * v[i].y + v[i].z * v[i].z + v[i].w * v[i].w;
#pragma unroll
        for (int o = 16; o > 0; o >>= 1) s += __shfl_xor_sync(0xFFFFFFFFu, s, o);

        // spin until threshold is published (producers never wait; they own
        // the lowest block IDs and are dispatched first)
        if (lane == 0) {
            while (*(volatile int*)&g_ready == 0) __nanosleep(64);
        }
        __syncwarp();
        __threadfence();   // acquire
        const float thresh = g_x2thresh;

        bool clipped = (s > thresh);
        if (!clipped) {
            // Stage 2: exact x2 (remaining 1280 elems)
            float s2 = 0.0f;
#pragma unroll
            for (int i = 6; i < 16; i++) {
                float4 w4 = __ldcs(xr + lane + 32 * i);
                s2 += w4.x * w4.x + w4.y * w4.y + w4.z * w4.z + w4.w * w4.w;
            }
#pragma unroll
            for (int o = 16; o > 0; o >>= 1)
                s2 += __shfl_xor_sync(0xFFFFFFFFu, s2, o);
            s += s2;
            clipped = (s > thresh);
        }

        float4* prow = (float4*)(p + (size_t)n * H_);

        if (clipped) {
            const float C = __uint_as_float(CLIP_P_BITS);
            const float4 c4 = make_float4(C, C, C, C);
#pragma unroll
            for (int i = 0; i < 8; i++) __stcs(prow + lane + 32 * i, c4);
            if (lane == 0) y[n] = g_yconst;
        } else {
            // Exact fallback for an unproven row (insurance; ~never runs).
            float z = 0.0f;
            for (int h = 0; h < H_; h++) {
                const float4* mr = (const float4*)(Mu + (size_t)h * D_);
                float dot = 0.0f;
#pragma unroll
                for (int i = 0; i < 16; i++) {
                    float4 a4 = xr[lane + 32 * i];
                    float4 b4 = mr[lane + 32 * i];
                    dot += a4.x * b4.x + a4.y * b4.y + a4.z * b4.z + a4.w * b4.w;
                }
#pragma unroll
                for (int o = 16; o > 0; o >>= 1)
                    dot += __shfl_xor_sync(0xFFFFFFFFu, dot, o);
                float sd = Sd[h];
                float power = -0.5f * (s - 2.0f * dot + g_mu2[h]) / (sd * sd);
                power = fminf(fmaxf(power, -100.0f), 40.0f);
                float pv = expf(power);
                if (lane == 0) { p[(size_t)n * H_ + h] = pv; z += pv * W[h]; }
            }
            if (lane == 0) {
                float tt = mul_rn(2.0f / 3.0f, z);
                float th = (fabsf(tt) < 1e-5f) ? tt : tanhf(tt);
                y[n] = mul_rn(1.7159f, th);
            }
        }

        // self-reset for the next graph replay: the LAST consumer block to
        // finish clears all flags/counters (no one reads them anymore).
        __syncthreads();
        if (t == 0) {
            __threadfence();
            int c = atomicAdd(&g_done, 1);
            if (c == GRID_MAIN - 1) {
                g_ready = 0;
                g_count = 0;
                g_done = 0;
                g_maxmu2_bits = 0;
                __threadfence();
            }
        }
    }
}

extern "C" void kernel_launch(void* const* d_in, const int* in_sizes, int n_in,
                              void* d_out, int out_size) {
    const float* x  = (const float*)d_in[0];
    const float* Mu = (const float*)d_in[1];
    const float* Sd = (const float*)d_in[2];
    const float* W  = (const float*)d_in[3];
    float* y = (float*)d_out;          // first N_ elements
    float* p = (float*)d_out + N_;     // then N_*H_ elements

    k_all<<<GRID_ALL, 256>>>(x, Mu, Sd, W, y, p);
}

// round 5
// speedup vs baseline: 1.3681x; 1.3681x over previous
#include <cuda_runtime.h>
#include <math.h>

#define N_ 16384
#define D_ 2048
#define H_ 1024

// fp32(exp(-100)) = 27 * 2^-149 (subnormal), bit pattern 0x0000001B.
#define CLIP_P_BITS 27u

// ---------------- scratch (device globals; no allocation allowed) ----------
__device__ float g_mu2[H_];        // ||mu_h||^2 (fallback path)
__device__ int   g_maxmu2_bits;    // atomicMax over mu2 (nonneg -> int order ok)
__device__ int   g_count;          // last-block-done counter (self-resetting)
__device__ float g_maxsd2;
__device__ float g_zconst;         // exact subnormal z for a clipped row
__device__ float g_yconst;         // y for a clipped row
__device__ float g_x2thresh;       // row clips if (partial) x2 > this

// Non-FTZ fp32 ops (immune to any -ftz / fast-math compile flags).
__device__ __forceinline__ float mul_rn(float a, float b) {
    float c; asm("mul.rn.f32 %0, %1, %2;" : "=f"(c) : "f"(a), "f"(b)); return c;
}
__device__ __forceinline__ float add_rn(float a, float b) {
    float c; asm("add.rn.f32 %0, %1, %2;" : "=f"(c) : "f"(a), "f"(b)); return c;
}

// ---------------- K1: prologue (PDL primary) --------------------------------
// 256 blocks x 256 threads; 4 Mu rows per block, 64 threads per row,
// 8 independent float4 loads per thread (MLP=8).
__global__ void __launch_bounds__(256) k_pre(const float* __restrict__ Mu,
                                             const float* __restrict__ Sd,
                                             const float* __restrict__ W) {
    // Signal PDL dependents immediately: k_main may launch and start its
    // x loads while we compute. It calls griddepcontrol.wait before reading
    // anything we write, which waits for our FULL completion + visibility.
    asm volatile("griddepcontrol.launch_dependents;" ::: "memory");

    __shared__ float sh[256];
    __shared__ float sh2[256];
    const int t = threadIdx.x;
    const int sub  = t >> 6;          // 0..3  (row within block)
    const int l64  = t & 63;          // 0..63
    const int row  = blockIdx.x * 4 + sub;

    const float4* r = (const float4*)(Mu + (size_t)row * D_);
    float s = 0.0f;
#pragma unroll
    for (int i = 0; i < 8; i++) {
        float4 v = r[l64 + 64 * i];
        s += v.x * v.x + v.y * v.y + v.z * v.z + v.w * v.w;
    }
    // reduce across 64 threads (2 warps): shfl within warp, combine in smem
#pragma unroll
    for (int o = 16; o > 0; o >>= 1) s += __shfl_xor_sync(0xFFFFFFFFu, s, o);
    if ((t & 31) == 0) sh[t >> 5] = s;   // 8 partials per block
    __syncthreads();
    if (t < 4) {
        float m2 = sh[2 * t] + sh[2 * t + 1];
        g_mu2[blockIdx.x * 4 + t] = m2;
        atomicMax(&g_maxmu2_bits, __float_as_int(m2));
    }
    __syncthreads();

    if (blockIdx.x == 0) {
        // maxsd2 + exact subnormal z over 1024 (4 per thread)
        float msd = 0.0f;
        const float C = __uint_as_float(CLIP_P_BITS);
        float zp = 0.0f;
#pragma unroll
        for (int i = 0; i < 4; i++) {
            float sd = Sd[t + 256 * i];
            msd = fmaxf(msd, sd * sd);
            // exact: products are multiples of 2^-149, |sum| << 2^-126,
            // so fp32 adds are exact and order-independent.
            zp = add_rn(zp, mul_rn(C, W[t + 256 * i]));
        }
        sh[t] = msd;
        sh2[t] = zp;
        __syncthreads();
        for (int o = 128; o > 0; o >>= 1) {
            if (t < o) {
                sh[t] = fmaxf(sh[t], sh[t + o]);
                sh2[t] = add_rn(sh2[t], sh2[t + o]);
            }
            __syncthreads();
        }
        if (t == 0) {
            g_maxsd2 = sh[0];
            float z = sh2[0];
            g_zconst = z;
            float tt = mul_rn(2.0f / 3.0f, z);                // subnormal-safe
            float th = (fabsf(tt) < 1e-5f) ? tt : tanhf(tt);  // tanh(x)==x tiny
            g_yconst = mul_rn(1.7159f, th);
        }
        __syncthreads();
    }

    if (t == 0) {
        __threadfence();
        int c = atomicAdd(&g_count, 1);
        if (c == (int)gridDim.x - 1) {   // last block: publish threshold
            __threadfence();
            float maxmu2 = __int_as_float(g_maxmu2_bits);
            float maxsd2 = g_maxsd2;
            // Row n clips for ALL h iff dist(n,h) > 200*sd_h^2 for all h.
            // Cauchy-Schwarz: dist >= (sqrt(x2)-sqrt(mu2_h))^2 when x2>mu2_h.
            // Margins cover our fp error AND the reference's fp32 GEMM error.
            float rhs = sqrtf(maxmu2) + sqrtf(200.0f * maxsd2 * 1.001f + 4.0f);
            g_x2thresh = rhs * rhs;
            // reset for next graph replay
            g_maxmu2_bits = 0;
            g_count = 0;
            __threadfence();
        }
    }
}

// ---------------- K2: fused main (PDL secondary) ----------------------------
// 2048 blocks x 256 threads; warp per x row. Stage-1 loads are issued BEFORE
// griddepcontrol.wait so they overlap k_pre's execution.
__global__ void __launch_bounds__(256, 4) k_main(const float* __restrict__ x,
                                                 const float* __restrict__ Mu,
                                                 const float* __restrict__ Sd,
                                                 const float* __restrict__ W,
                                                 float* __restrict__ y,
                                                 float* __restrict__ p) {
    const int warp = threadIdx.x >> 5;
    const int lane = threadIdx.x & 31;
    const int n    = blockIdx.x * 8 + warp;
    const float4* xr = (const float4*)(x + (size_t)n * D_);

    // Stage 1: lower bound on ||x_n||^2 from first 768 elems
    // (sums of squares are monotone, so a prefix is a valid lower bound)
    float4 v[6];
#pragma unroll
    for (int i = 0; i < 6; i++) v[i] = __ldcs(xr + lane + 32 * i);
    float s = 0.0f;
#pragma unroll
    for (int i = 0; i < 6; i++)
        s += v[i].x * v[i].x + v[i].y * v[i].y + v[i].z * v[i].z + v[i].w * v[i].w;
#pragma unroll
    for (int o = 16; o > 0; o >>= 1) s += __shfl_xor_sync(0xFFFFFFFFu, s, o);

    // Wait for k_pre completion (+ memory visibility). HW wait, not a spin.
    asm volatile("griddepcontrol.wait;" ::: "memory");
    const float thresh = g_x2thresh;

    bool clipped = (s > thresh);
    if (!clipped) {
        // Stage 2: exact x2 (remaining 1280 elems)
        float s2 = 0.0f;
#pragma unroll
        for (int i = 6; i < 16; i++) {
            float4 w4 = __ldcs(xr + lane + 32 * i);
            s2 += w4.x * w4.x + w4.y * w4.y + w4.z * w4.z + w4.w * w4.w;
        }
#pragma unroll
        for (int o = 16; o > 0; o >>= 1) s2 += __shfl_xor_sync(0xFFFFFFFFu, s2, o);
        s += s2;
        clipped = (s > thresh);
    }

    float4* prow = (float4*)(p + (size_t)n * H_);

    if (clipped) {
        const float C = __uint_as_float(CLIP_P_BITS);
        const float4 c4 = make_float4(C, C, C, C);
#pragma unroll
        for (int i = 0; i < 8; i++) __stcs(prow + lane + 32 * i, c4);
        if (lane == 0) y[n] = g_yconst;
    } else {
        // Exact fallback for an unproven row (insurance; ~never runs).
        // Deliberately scalar + unroll-1 to keep the cold path's register
        // footprint from throttling the hot path's occupancy.
        const float* xs = (const float*)xr;
        float z = 0.0f;
#pragma unroll 1
        for (int h = 0; h < H_; h++) {
            const float* mr = Mu + (size_t)h * D_;
            float dot = 0.0f;
#pragma unroll 1
            for (int k = lane; k < D_; k += 32) dot += xs[k] * mr[k];
#pragma unroll
            for (int o = 16; o > 0; o >>= 1)
                dot += __shfl_xor_sync(0xFFFFFFFFu, dot, o);
            float sd = Sd[h];
            float power = -0.5f * (s - 2.0f * dot + g_mu2[h]) / (sd * sd);
            power = fminf(fmaxf(power, -100.0f), 40.0f);
            float pv = expf(power);
            if (lane == 0) { p[(size_t)n * H_ + h] = pv; z += pv * W[h]; }
        }
        if (lane == 0) {
            float tt = mul_rn(2.0f / 3.0f, z);
            float th = (fabsf(tt) < 1e-5f) ? tt : tanhf(tt);
            y[n] = mul_rn(1.7159f, th);
        }
    }
}

extern "C" void kernel_launch(void* const* d_in, const int* in_sizes, int n_in,
                              void* d_out, int out_size) {
    const float* x  = (const float*)d_in[0];
    const float* Mu = (const float*)d_in[1];
    const float* Sd = (const float*)d_in[2];
    const float* W  = (const float*)d_in[3];
    float* y = (float*)d_out;          // first N_ elements
    float* p = (float*)d_out + N_;     // then N_*H_ elements

    k_pre<<<256, 256>>>(Mu, Sd, W);

    // k_main with Programmatic Dependent Launch: it may begin executing while
    // k_pre is still running; it synchronizes in-kernel via griddepcontrol.wait.
    cudaLaunchAttribute attrs[1];
    attrs[0].id = cudaLaunchAttributeProgrammaticStreamSerialization;
    attrs[0].val.programmaticStreamSerializationAllowed = 1;

    cudaLaunchConfig_t cfg = {};
    cfg.gridDim  = dim3(2048, 1, 1);
    cfg.blockDim = dim3(256, 1, 1);
    cfg.dynamicSmemBytes = 0;
    cfg.stream = 0;            // legacy default stream (the captured stream)
    cfg.attrs = attrs;
    cfg.numAttrs = 1;

    cudaLaunchKernelEx(&cfg, k_main, x, Mu, Sd, W, y, p);
}

// round 6
// speedup vs baseline: 1.4396x; 1.0522x over previous
#include <cuda_runtime.h>
#include <math.h>

#define N_ 16384
#define D_ 2048
#define H_ 1024

// fp32(exp(-100)) = 27 * 2^-149 (subnormal), bit pattern 0x0000001B.
#define CLIP_P_BITS 27u

// ---------------- scratch (device globals; no allocation allowed) ----------
__device__ float g_mu2[H_];        // ||mu_h||^2 (fallback path)
__device__ int   g_maxmu2_bits;    // atomicMax over mu2 (nonneg -> int order ok)
__device__ int   g_count;          // last-block-done counter (self-resetting)
__device__ float g_maxsd2;
__device__ float g_zconst;         // exact subnormal z for a clipped row
__device__ float g_yconst;         // y for a clipped row
__device__ float g_x2thresh;       // row clips if (partial) x2 > this

// Non-FTZ fp32 ops (immune to any -ftz / fast-math compile flags).
__device__ __forceinline__ float mul_rn(float a, float b) {
    float c; asm("mul.rn.f32 %0, %1, %2;" : "=f"(c) : "f"(a), "f"(b)); return c;
}
__device__ __forceinline__ float add_rn(float a, float b) {
    float c; asm("add.rn.f32 %0, %1, %2;" : "=f"(c) : "f"(a), "f"(b)); return c;
}

// ---------------- K1: prologue (PDL primary) --------------------------------
// 256 blocks x 256 threads; 4 Mu rows per block, 64 threads per row,
// 8 independent float4 loads per thread (MLP=8). Default cache policy so the
// 8 MB of Mu can stay L2-resident across graph replays.
__global__ void __launch_bounds__(256) k_pre(const float* __restrict__ Mu,
                                             const float* __restrict__ Sd,
                                             const float* __restrict__ W) {
    // Signal PDL dependents immediately: k_main may launch and start its
    // x loads while we compute. It calls griddepcontrol.wait before reading
    // anything we write, which waits for our FULL completion + visibility.
    asm volatile("griddepcontrol.launch_dependents;" ::: "memory");

    __shared__ float sh[256];
    __shared__ float sh2[256];
    const int t = threadIdx.x;
    const int sub  = t >> 6;          // 0..3  (row within block)
    const int l64  = t & 63;          // 0..63
    const int row  = blockIdx.x * 4 + sub;

    const float4* r = (const float4*)(Mu + (size_t)row * D_);
    float s = 0.0f;
#pragma unroll
    for (int i = 0; i < 8; i++) {
        float4 v = r[l64 + 64 * i];
        s += v.x * v.x + v.y * v.y + v.z * v.z + v.w * v.w;
    }
    // reduce across 64 threads (2 warps): shfl within warp, combine in smem
#pragma unroll
    for (int o = 16; o > 0; o >>= 1) s += __shfl_xor_sync(0xFFFFFFFFu, s, o);
    if ((t & 31) == 0) sh[t >> 5] = s;   // 8 partials per block
    __syncthreads();
    if (t < 4) {
        float m2 = sh[2 * t] + sh[2 * t + 1];
        g_mu2[blockIdx.x * 4 + t] = m2;
        atomicMax(&g_maxmu2_bits, __float_as_int(m2));
    }
    __syncthreads();

    if (blockIdx.x == 0) {
        // maxsd2 + exact subnormal z over 1024 (4 per thread)
        float msd = 0.0f;
        const float C = __uint_as_float(CLIP_P_BITS);
        float zp = 0.0f;
#pragma unroll
        for (int i = 0; i < 4; i++) {
            float sd = Sd[t + 256 * i];
            msd = fmaxf(msd, sd * sd);
            // exact: products are multiples of 2^-149, |sum| << 2^-126,
            // so fp32 adds are exact and order-independent.
            zp = add_rn(zp, mul_rn(C, W[t + 256 * i]));
        }
        sh[t] = msd;
        sh2[t] = zp;
        __syncthreads();
        for (int o = 128; o > 0; o >>= 1) {
            if (t < o) {
                sh[t] = fmaxf(sh[t], sh[t + o]);
                sh2[t] = add_rn(sh2[t], sh2[t + o]);
            }
            __syncthreads();
        }
        if (t == 0) {
            g_maxsd2 = sh[0];
            float z = sh2[0];
            g_zconst = z;
            float tt = mul_rn(2.0f / 3.0f, z);                // subnormal-safe
            float th = (fabsf(tt) < 1e-5f) ? tt : tanhf(tt);  // tanh(x)==x tiny
            g_yconst = mul_rn(1.7159f, th);
        }
        __syncthreads();
    }

    if (t == 0) {
        __threadfence();
        int c = atomicAdd(&g_count, 1);
        if (c == (int)gridDim.x - 1) {   // last block: publish threshold
            __threadfence();
            float maxmu2 = __int_as_float(g_maxmu2_bits);
            float maxsd2 = g_maxsd2;
            // Row n clips for ALL h iff dist(n,h) > 200*sd_h^2 for all h.
            // Cauchy-Schwarz: dist >= (sqrt(x2)-sqrt(mu2_h))^2 when x2>mu2_h.
            // Margins cover our fp error AND the reference's fp32 GEMM error.
            float rhs = sqrtf(maxmu2) + sqrtf(200.0f * maxsd2 * 1.001f + 4.0f);
            g_x2thresh = rhs * rhs;
            // reset for next graph replay
            g_maxmu2_bits = 0;
            g_count = 0;
            __threadfence();
        }
    }
}

// ---------------- K2: fused main (PDL secondary) ----------------------------
// 2048 blocks x 256 threads; warp per x row. Stage-1 loads are issued BEFORE
// griddepcontrol.wait so they overlap k_pre's execution.
// Cache policy: x prefix reads use DEFAULT eviction (the ~50 MB prefix can
// stay L2-resident across graph replays); p stores use __stcs (evict-first:
// they must drain to DRAM anyway, and this protects the cached x prefix).
__global__ void __launch_bounds__(256, 5) k_main(const float* __restrict__ x,
                                                 const float* __restrict__ Mu,
                                                 const float* __restrict__ Sd,
                                                 const float* __restrict__ W,
                                                 float* __restrict__ y,
                                                 float* __restrict__ p) {
    const int warp = threadIdx.x >> 5;
    const int lane = threadIdx.x & 31;
    const int n    = blockIdx.x * 8 + warp;
    const float4* xr = (const float4*)(x + (size_t)n * D_);

    // Stage 1: lower bound on ||x_n||^2 from first 768 elems
    // (sums of squares are monotone, so a prefix is a valid lower bound)
    float4 v[6];
#pragma unroll
    for (int i = 0; i < 6; i++) v[i] = xr[lane + 32 * i];
    float s = 0.0f;
#pragma unroll
    for (int i = 0; i < 6; i++)
        s += v[i].x * v[i].x + v[i].y * v[i].y + v[i].z * v[i].z + v[i].w * v[i].w;
#pragma unroll
    for (int o = 16; o > 0; o >>= 1) s += __shfl_xor_sync(0xFFFFFFFFu, s, o);

    // Wait for k_pre completion (+ memory visibility). HW wait, not a spin.
    asm volatile("griddepcontrol.wait;" ::: "memory");
    const float thresh = g_x2thresh;

    bool clipped = (s > thresh);
    if (!clipped) {
        // Stage 2: exact x2 (remaining 1280 elems; rare, keep evict-first)
        float s2 = 0.0f;
#pragma unroll
        for (int i = 6; i < 16; i++) {
            float4 w4 = __ldcs(xr + lane + 32 * i);
            s2 += w4.x * w4.x + w4.y * w4.y + w4.z * w4.z + w4.w * w4.w;
        }
#pragma unroll
        for (int o = 16; o > 0; o >>= 1) s2 += __shfl_xor_sync(0xFFFFFFFFu, s2, o);
        s += s2;
        clipped = (s > thresh);
    }

    float4* prow = (float4*)(p + (size_t)n * H_);

    if (clipped) {
        const float C = __uint_as_float(CLIP_P_BITS);
        const float4 c4 = make_float4(C, C, C, C);
#pragma unroll
        for (int i = 0; i < 8; i++) __stcs(prow + lane + 32 * i, c4);
        if (lane == 0) y[n] = g_yconst;
    } else {
        // Exact fallback for an unproven row (insurance; ~never runs).
        // Deliberately scalar + unroll-1 to keep the cold path's register
        // footprint from throttling the hot path's occupancy.
        const float* xs = (const float*)xr;
        float z = 0.0f;
#pragma unroll 1
        for (int h = 0; h < H_; h++) {
            const float* mr = Mu + (size_t)h * D_;
            float dot = 0.0f;
#pragma unroll 1
            for (int k = lane; k < D_; k += 32) dot += xs[k] * mr[k];
#pragma unroll
            for (int o = 16; o > 0; o >>= 1)
                dot += __shfl_xor_sync(0xFFFFFFFFu, dot, o);
            float sd = Sd[h];
            float power = -0.5f * (s - 2.0f * dot + g_mu2[h]) / (sd * sd);
            power = fminf(fmaxf(power, -100.0f), 40.0f);
            float pv = expf(power);
            if (lane == 0) { p[(size_t)n * H_ + h] = pv; z += pv * W[h]; }
        }
        if (lane == 0) {
            float tt = mul_rn(2.0f / 3.0f, z);
            float th = (fabsf(tt) < 1e-5f) ? tt : tanhf(tt);
            y[n] = mul_rn(1.7159f, th);
        }
    }
}

extern "C" void kernel_launch(void* const* d_in, const int* in_sizes, int n_in,
                              void* d_out, int out_size) {
    const float* x  = (const float*)d_in[0];
    const float* Mu = (const float*)d_in[1];
    const float* Sd = (const float*)d_in[2];
    const float* W  = (const float*)d_in[3];
    float* y = (float*)d_out;          // first N_ elements
    float* p = (float*)d_out + N_;     // then N_*H_ elements

    k_pre<<<256, 256>>>(Mu, Sd, W);

    // k_main with Programmatic Dependent Launch: it may begin executing while
    // k_pre is still running; it synchronizes in-kernel via griddepcontrol.wait.
    cudaLaunchAttribute attrs[1];
    attrs[0].id = cudaLaunchAttributeProgrammaticStreamSerialization;
    attrs[0].val.programmaticStreamSerializationAllowed = 1;

    cudaLaunchConfig_t cfg = {};
    cfg.gridDim  = dim3(2048, 1, 1);
    cfg.blockDim = dim3(256, 1, 1);
    cfg.dynamicSmemBytes = 0;
    cfg.stream = 0;            // legacy default stream (the captured stream)
    cfg.attrs = attrs;
    cfg.numAttrs = 1;

    cudaLaunchKernelEx(&cfg, k_main, x, Mu, Sd, W, y, p);
}

// round 7
// speedup vs baseline: 1.5976x; 1.1098x over previous
#include <cuda_runtime.h>
#include <math.h>

#define N_ 16384
#define D_ 2048
#define H_ 1024

// fp32(exp(-100)) = 27 * 2^-149 (subnormal), bit pattern 0x0000001B.
#define CLIP_P_BITS 27u

// ---------------- scratch (device globals; no allocation allowed) ----------
__device__ float g_mu2[H_];        // ||mu_h||^2 (fallback path)
__device__ int   g_maxmu2_bits;    // atomicMax over mu2 (nonneg -> int order ok)
__device__ int   g_count;          // last-block-done counter (self-resetting)
__device__ float g_maxsd2;
__device__ float g_zconst;         // exact subnormal z for a clipped row
__device__ float g_yconst;         // y for a clipped row
__device__ float g_x2thresh;       // row clips if (partial) x2 > this

// Non-FTZ fp32 ops (immune to any -ftz / fast-math compile flags).
__device__ __forceinline__ float mul_rn(float a, float b) {
    float c; asm("mul.rn.f32 %0, %1, %2;" : "=f"(c) : "f"(a), "f"(b)); return c;
}
__device__ __forceinline__ float add_rn(float a, float b) {
    float c; asm("add.rn.f32 %0, %1, %2;" : "=f"(c) : "f"(a), "f"(b)); return c;
}

// ---------------- K1: prologue (PDL primary) --------------------------------
// 1024 blocks x 256 threads; one Mu row per block (2 float4/thread), so the
// 8 MB Mu read finishes near its ~1.3 us bandwidth floor.
__global__ void __launch_bounds__(256) k_pre(const float* __restrict__ Mu,
                                             const float* __restrict__ Sd,
                                             const float* __restrict__ W) {
    // Signal PDL dependents immediately: k_main may launch, stream its x
    // loads AND its speculative p stores while we compute.
    asm volatile("griddepcontrol.launch_dependents;" ::: "memory");

    __shared__ float sh[256];
    __shared__ float sh2[256];
    const int t = threadIdx.x;
    const int row = blockIdx.x;

    const float4* r = (const float4*)(Mu + (size_t)row * D_);
    float4 a = r[t], b = r[t + 256];
    float s = a.x * a.x + a.y * a.y + a.z * a.z + a.w * a.w
            + b.x * b.x + b.y * b.y + b.z * b.z + b.w * b.w;
#pragma unroll
    for (int o = 16; o > 0; o >>= 1) s += __shfl_xor_sync(0xFFFFFFFFu, s, o);
    if ((t & 31) == 0) sh[t >> 5] = s;     // 8 warp partials
    __syncthreads();
    if (t == 0) {
        float m2 = 0.0f;
#pragma unroll
        for (int i = 0; i < 8; i++) m2 += sh[i];
        g_mu2[row] = m2;
        atomicMax(&g_maxmu2_bits, __float_as_int(m2));
    }
    __syncthreads();

    if (blockIdx.x == 0) {
        // maxsd2 + exact subnormal z over 1024 (4 per thread)
        float msd = 0.0f;
        const float C = __uint_as_float(CLIP_P_BITS);
        float zp = 0.0f;
#pragma unroll
        for (int i = 0; i < 4; i++) {
            float sd = Sd[t + 256 * i];
            msd = fmaxf(msd, sd * sd);
            // exact: products are multiples of 2^-149, |sum| << 2^-126,
            // so fp32 adds are exact and order-independent.
            zp = add_rn(zp, mul_rn(C, W[t + 256 * i]));
        }
        sh[t] = msd;
        sh2[t] = zp;
        __syncthreads();
        for (int o = 128; o > 0; o >>= 1) {
            if (t < o) {
                sh[t] = fmaxf(sh[t], sh[t + o]);
                sh2[t] = add_rn(sh2[t], sh2[t + o]);
            }
            __syncthreads();
        }
        if (t == 0) {
            g_maxsd2 = sh[0];
            float z = sh2[0];
            g_zconst = z;
            float tt = mul_rn(2.0f / 3.0f, z);                // subnormal-safe
            float th = (fabsf(tt) < 1e-5f) ? tt : tanhf(tt);  // tanh(x)==x tiny
            g_yconst = mul_rn(1.7159f, th);
        }
        __syncthreads();
    }

    if (t == 0) {
        __threadfence();
        int c = atomicAdd(&g_count, 1);
        if (c == (int)gridDim.x - 1) {   // last block: publish threshold
            __threadfence();
            float maxmu2 = __int_as_float(g_maxmu2_bits);
            float maxsd2 = g_maxsd2;
            // Row n clips for ALL h iff dist(n,h) > 200*sd_h^2 for all h.
            // Cauchy-Schwarz: dist >= (sqrt(x2)-sqrt(mu2_h))^2 when x2>mu2_h.
            // Margins cover our fp error AND the reference's fp32 GEMM error.
            float rhs = sqrtf(maxmu2) + sqrtf(200.0f * maxsd2 * 1.001f + 4.0f);
            g_x2thresh = rhs * rhs;
            // reset for next graph replay
            g_maxmu2_bits = 0;
            g_count = 0;
            __threadfence();
        }
    }
}

// ---------------- K2: fused main (PDL secondary) ----------------------------
// 2048 blocks x 256 threads; warp per x row.
// KEY ORDERING: stage-1 x loads and the SPECULATIVE p-row fill (value C is
// input-independent) are issued BEFORE griddepcontrol.wait, so k_pre's whole
// runtime hides under this kernel's streaming. The wait only gates the tiny
// y-write and the ~never-taken verification fallback, which overwrites the
// speculative row lane-consistently (same thread, same address => ordered).
__global__ void __launch_bounds__(256, 5) k_main(const float* __restrict__ x,
                                                 const float* __restrict__ Mu,
                                                 const float* __restrict__ Sd,
                                                 const float* __restrict__ W,
                                                 float* __restrict__ y,
                                                 float* __restrict__ p) {
    const int warp = threadIdx.x >> 5;
    const int lane = threadIdx.x & 31;
    const int n    = blockIdx.x * 8 + warp;
    const float4* xr = (const float4*)(x + (size_t)n * D_);
    float4* prow = (float4*)(p + (size_t)n * H_);

    // Stage 1: lower bound on ||x_n||^2 from first 768 elems
    // (sums of squares are monotone, so a prefix is a valid lower bound)
    float4 v[6];
#pragma unroll
    for (int i = 0; i < 6; i++) v[i] = xr[lane + 32 * i];

    // Speculative fill: p[n,:] = exp(-100). Correct for ~every row; the rare
    // unproven row is recomputed and overwritten below after verification.
    const float C = __uint_as_float(CLIP_P_BITS);
    const float4 c4 = make_float4(C, C, C, C);
#pragma unroll
    for (int i = 0; i < 8; i++) __stcs(prow + lane + 32 * i, c4);

    float s = 0.0f;
#pragma unroll
    for (int i = 0; i < 6; i++)
        s += v[i].x * v[i].x + v[i].y * v[i].y + v[i].z * v[i].z + v[i].w * v[i].w;
#pragma unroll
    for (int o = 16; o > 0; o >>= 1) s += __shfl_xor_sync(0xFFFFFFFFu, s, o);

    // Wait for k_pre completion (+ memory visibility). HW wait, not a spin.
    asm volatile("griddepcontrol.wait;" ::: "memory");
    const float thresh = g_x2thresh;

    bool clipped = (s > thresh);
    if (!clipped) {
        // Stage 2: exact x2 (remaining 1280 elems; rare)
        float s2 = 0.0f;
#pragma unroll
        for (int i = 6; i < 16; i++) {
            float4 w4 = __ldcs(xr + lane + 32 * i);
            s2 += w4.x * w4.x + w4.y * w4.y + w4.z * w4.z + w4.w * w4.w;
        }
#pragma unroll
        for (int o = 16; o > 0; o >>= 1) s2 += __shfl_xor_sync(0xFFFFFFFFu, s2, o);
        s += s2;
        clipped = (s > thresh);
    }

    if (clipped) {
        if (lane == 0) y[n] = g_yconst;   // speculative p row already correct
    } else {
        // Exact fallback for an unproven row (insurance; ~never runs).
        // Each store is issued by the SAME lane that wrote that address in
        // the speculative fill (lane owns h where ((h>>2)&31)==lane), so the
        // overwrite is same-thread program-ordered -- no race.
        const float* xs = (const float*)xr;
        float z = 0.0f;
#pragma unroll 1
        for (int h = 0; h < H_; h++) {
            const float* mr = Mu + (size_t)h * D_;
            float dot = 0.0f;
#pragma unroll 1
            for (int k = lane; k < D_; k += 32) dot += xs[k] * mr[k];
#pragma unroll
            for (int o = 16; o > 0; o >>= 1)
                dot += __shfl_xor_sync(0xFFFFFFFFu, dot, o);
            float sd = Sd[h];
            float power = -0.5f * (s - 2.0f * dot + g_mu2[h]) / (sd * sd);
            power = fminf(fmaxf(power, -100.0f), 40.0f);
            float pv = expf(power);
            if (lane == ((h >> 2) & 31)) p[(size_t)n * H_ + h] = pv;
            if (lane == 0) z += pv * W[h];
        }
        if (lane == 0) {
            float tt = mul_rn(2.0f / 3.0f, z);
            float th = (fabsf(tt) < 1e-5f) ? tt : tanhf(tt);
            y[n] = mul_rn(1.7159f, th);
        }
    }
}

extern "C" void kernel_launch(void* const* d_in, const int* in_sizes, int n_in,
                              void* d_out, int out_size) {
    const float* x  = (const float*)d_in[0];
    const float* Mu = (const float*)d_in[1];
    const float* Sd = (const float*)d_in[2];
    const float* W  = (const float*)d_in[3];
    float* y = (float*)d_out;          // first N_ elements
    float* p = (float*)d_out + N_;     // then N_*H_ elements

    k_pre<<<1024, 256>>>(Mu, Sd, W);

    // k_main with Programmatic Dependent Launch: it begins executing while
    // k_pre is still running; it synchronizes in-kernel via griddepcontrol.wait.
    cudaLaunchAttribute attrs[1];
    attrs[0].id = cudaLaunchAttributeProgrammaticStreamSerialization;
    attrs[0].val.programmaticStreamSerializationAllowed = 1;

    cudaLaunchConfig_t cfg = {};
    cfg.gridDim  = dim3(2048, 1, 1);
    cfg.blockDim = dim3(256, 1, 1);
    cfg.dynamicSmemBytes = 0;
    cfg.stream = 0;            // legacy default stream (the captured stream)
    cfg.attrs = attrs;
    cfg.numAttrs = 1;

    cudaLaunchKernelEx(&cfg, k_main, x, Mu, Sd, W, y, p);
}